// round 3
// baseline (speedup 1.0000x reference)
#include <cuda_runtime.h>
#include <cuda_bf16.h>
#include <math.h>

// Problem constants (fixed by the dataset)
#define NN    50000
#define DEG   16
#define EDGES (NN * DEG)      // 800000
#define DIM   128
#define HID   128

#define NPB   16              // nodes per block (kernel 2)
#define EPB   256             // edges per block
#define K2T   512             // threads (kernel 2)

// Persistent scratch: layer-1 node projections A = F @ W1[0:128], B = F @ W1[128:256]
__device__ float g_A[NN * DIM];
__device__ float g_B[NN * DIM];

// ---------------------------------------------------------------------------
// Kernel 1: AB = features[N,128] @ Wcat[128,256]. Tiled fp32 GEMM.
// ---------------------------------------------------------------------------
#define K1_SMEM_FLOATS (64 * 132 + 128 * 68)

__global__ void layer1_gemm_kernel(const float* __restrict__ feat,
                                   const float* __restrict__ w1) {
    extern __shared__ float smem1[];
    float* featS = smem1;              // [64][132]
    float* wS    = smem1 + 64 * 132;   // [128][68]

    const int tid = threadIdx.x;
    const int m0 = blockIdx.x * 64;
    const int n0 = blockIdx.y * 64;

    for (int t = tid; t < 64 * 32; t += 256) {
        int r = t >> 5, c4 = (t & 31) << 2;
        int gr = m0 + r;
        float4 v = make_float4(0.f, 0.f, 0.f, 0.f);
        if (gr < NN) v = *(const float4*)&feat[gr * DIM + c4];
        *(float4*)&featS[r * 132 + c4] = v;
    }
    for (int t = tid; t < 128 * 16; t += 256) {
        int k = t >> 4, c4 = (t & 15) << 2;
        int n = n0 + c4;
        const float* src = (n < 128) ? &w1[k * 128 + n]
                                     : &w1[(128 + k) * 128 + (n - 128)];
        *(float4*)&wS[k * 68 + c4] = *(const float4*)src;
    }
    __syncthreads();

    const int ty = tid >> 4, tx = tid & 15;
    const int r0 = ty * 4, c0 = tx * 4;
    float acc[4][4];
#pragma unroll
    for (int i = 0; i < 4; ++i)
#pragma unroll
        for (int j = 0; j < 4; ++j) acc[i][j] = 0.f;

#pragma unroll 4
    for (int k = 0; k < 128; ++k) {
        float a[4];
#pragma unroll
        for (int i = 0; i < 4; ++i) a[i] = featS[(r0 + i) * 132 + k];
        float4 bq = *(const float4*)&wS[k * 68 + c0];
        float b[4] = {bq.x, bq.y, bq.z, bq.w};
#pragma unroll
        for (int i = 0; i < 4; ++i)
#pragma unroll
            for (int j = 0; j < 4; ++j) acc[i][j] = fmaf(a[i], b[j], acc[i][j]);
    }

#pragma unroll
    for (int i = 0; i < 4; ++i) {
        int node = m0 + r0 + i;
        if (node >= NN) continue;
        int n = n0 + c0;
        float4 o = make_float4(acc[i][0], acc[i][1], acc[i][2], acc[i][3]);
        if (n < 128) *(float4*)&g_A[node * DIM + n] = o;
        else         *(float4*)&g_B[node * DIM + (n - 128)] = o;
    }
}

// ---------------------------------------------------------------------------
// Kernel 2: per block = 16 nodes = 256 edges, 512 threads.
//  Phase 1: h1T[j][el] = relu(A[row]+B[col]+v*w1[256,j]+b1[j])
//  Phase 2: warp-tiled GEMM (each warp: 128 edges x 16 cols slice; warp-uniform
//           broadcast w2 reads, coalesced h1 reads), fused relu + w3 partial dot
//  Phase 3: per-node softmax -> hard-concrete -> softmax -> top-8 mask
// ---------------------------------------------------------------------------
#define K2_SMEM_FLOATS (128 * EPB + 128 * 128 + EPB * 8 + 128 + 128 + 128 + 128 + EPB + EPB + EPB)

__global__ void __launch_bounds__(K2T, 1)
edge_mlp_mask_kernel(const int* __restrict__ colIdx,
                     const float* __restrict__ values,
                     const float* __restrict__ temperature,
                     const float* __restrict__ w1,
                     const float* __restrict__ b1,
                     const float* __restrict__ w2,
                     const float* __restrict__ b2,
                     const float* __restrict__ w3,
                     const float* __restrict__ b3,
                     float* __restrict__ out) {
    extern __shared__ float smem[];
    float* h1T   = smem;                      // [128(k)][256(el)]
    float* w2s   = h1T + 128 * EPB;           // [128(k)][128(j)]
    float* zred  = w2s + 128 * 128;           // [256(el)][8(grp)]
    float* b2s   = zred + EPB * 8;            // [128]
    float* w3s   = b2s + 128;                 // [128]
    float* b1s   = w3s + 128;                 // [128]
    float* w1rs  = b1s + 128;                 // [128]
    float* vals  = w1rs + 128;                // [256]
    float* zz    = vals + EPB;                // [256]
    int*   cols  = (int*)(zz + EPB);          // [256]

    const int tid = threadIdx.x;
    const int base_node = blockIdx.x * NPB;
    const int e0 = blockIdx.x * EPB;

    // ---- stage w2, b1/b2/w3, w1 value-row, colIdx, values ----
    for (int t = tid; t < 128 * 32; t += K2T) {
        int k = t >> 5, c4 = (t & 31) << 2;
        *(float4*)&w2s[k * 128 + c4] = *(const float4*)&w2[k * 128 + c4];
    }
    if (tid < 128) {
        b2s[tid]  = b2[tid];
        w3s[tid]  = w3[tid];
        b1s[tid]  = b1[tid];
        w1rs[tid] = w1[256 * 128 + tid];
    }
    if (tid < EPB) {
        cols[tid] = colIdx[e0 + tid];
        vals[tid] = values[e0 + tid];
    }
    __syncthreads();

    // ---- Phase 1: build h1T (transposed: feature-major, edge-minor) ----
    {
        const int el0 = (tid & 63) * 4;          // 4 consecutive edges (same node)
        const int jb  = tid >> 6;                // 0..7
        const int node = el0 >> 4;
        const float* gAr = &g_A[(base_node + node) * DIM];
        int4 c4 = *(const int4*)&cols[el0];
        float4 v4 = *(const float4*)&vals[el0];
#pragma unroll
        for (int it = 0; it < 16; ++it) {
            const int j = it * 8 + jb;
            const float b1j = b1s[j];
            const float wrj = w1rs[j];
            const float a = gAr[j] + b1j;
            float4 h;
            h.x = fmaf(v4.x, wrj, a + g_B[c4.x * DIM + j]);
            h.y = fmaf(v4.y, wrj, a + g_B[c4.y * DIM + j]);
            h.z = fmaf(v4.z, wrj, a + g_B[c4.z * DIM + j]);
            h.w = fmaf(v4.w, wrj, a + g_B[c4.w * DIM + j]);
            h.x = fmaxf(h.x, 0.f); h.y = fmaxf(h.y, 0.f);
            h.z = fmaxf(h.z, 0.f); h.w = fmaxf(h.w, 0.f);
            *(float4*)&h1T[j * EPB + el0] = h;
        }
    }
    __syncthreads();

    // ---- Phase 2: h2 = relu(h1 @ w2 + b2); z-partials = h2 @ w3 ----
    {
        const int w    = tid >> 5;        // warp 0..15
        const int lane = tid & 31;
        const int eh   = w >> 3;          // edge half
        const int grp  = w & 7;           // col group
        const int er0  = eh * 128 + lane * 4;
        const int jc0  = grp * 16;

        float acc[4][16];
#pragma unroll
        for (int i = 0; i < 4; ++i)
#pragma unroll
            for (int j = 0; j < 16; ++j) acc[i][j] = 0.f;

#pragma unroll 2
        for (int k = 0; k < 128; ++k) {
            float4 a4 = *(const float4*)&h1T[k * EPB + er0];   // coalesced
            float bv[16];                                      // warp-uniform (broadcast)
#pragma unroll
            for (int q = 0; q < 4; ++q)
                *(float4*)&bv[q * 4] = *(const float4*)&w2s[k * 128 + jc0 + q * 4];
            float av[4] = {a4.x, a4.y, a4.z, a4.w};
#pragma unroll
            for (int i = 0; i < 4; ++i)
#pragma unroll
                for (int j = 0; j < 16; ++j)
                    acc[i][j] = fmaf(av[i], bv[j], acc[i][j]);
        }
        // epilogue: relu + partial w3 dot over this warp's 16 cols
#pragma unroll
        for (int i = 0; i < 4; ++i) {
            float s = 0.f;
#pragma unroll
            for (int j = 0; j < 16; ++j) {
                float h2v = fmaxf(acc[i][j] + b2s[jc0 + j], 0.f);
                s = fmaf(h2v, w3s[jc0 + j], s);
            }
            zred[(er0 + i) * 8 + grp] = s;
        }
    }
    __syncthreads();

    if (tid < EPB) {
        float s = b3[0];
#pragma unroll
        for (int g = 0; g < 8; ++g) s += zred[tid * 8 + g];
        zz[tid] = s;
    }
    __syncthreads();

    // ---- Phase 3: per-node (warp w -> node w) softmax chain + top-8 mask ----
    {
        const unsigned FULL = 0xffffffffu;
        const int lane = tid & 31;
        const int l = lane & 15;
        const int wnode = tid >> 5;          // 0..15
        const int el = wnode * 16 + l;
        const float zv = zz[el];

        float m = zv;
#pragma unroll
        for (int o = 8; o >= 1; o >>= 1) m = fmaxf(m, __shfl_xor_sync(FULL, m, o, 16));
        float x1 = __fsub_rn(zv, m);
        float ev = (float)exp((double)x1);
        float s = 0.f;
#pragma unroll
        for (int o = 0; o < 16; ++o) s = __fadd_rn(s, __shfl_sync(FULL, ev, o, 16));
        float pi = __fdiv_rn(ev, s);

        float larg = __fadd_rn(pi, 1e-8f);
        float lg = (float)log((double)larg);
        float sx = __fdiv_rn(lg, temperature[0]);
        float hard = (float)(1.0 / (1.0 + exp(-(double)sx)));
        hard = fminf(fmaxf(hard, 0.f), 1.f);

        float m2 = hard;
#pragma unroll
        for (int o = 8; o >= 1; o >>= 1) m2 = fmaxf(m2, __shfl_xor_sync(FULL, m2, o, 16));
        float x2 = __fsub_rn(hard, m2);
        float e2 = (float)exp((double)x2);
        float s2 = 0.f;
#pragma unroll
        for (int o = 0; o < 16; ++o) s2 = __fadd_rn(s2, __shfl_sync(FULL, e2, o, 16));
        float y = __fdiv_rn(e2, s2);

        int r = 0;
#pragma unroll
        for (int o = 0; o < 16; ++o) {
            float yo = __shfl_sync(FULL, y, o, 16);
            r += (yo > y) || (yo == y && o < l);
        }
        unsigned bal = __ballot_sync(FULL, (r == 7) && (lane < 16));
        int src = __ffs(bal) - 1;
        float thre = __shfl_sync(FULL, y, src);

        float t = __fadd_rn(__fsub_rn(y, thre), 1e-7f);
        float outv = (t > 0.f) ? y : 0.f;
        if (lane < 16) out[e0 + el] = outv;
    }
}

// ---------------------------------------------------------------------------
extern "C" void kernel_launch(void* const* d_in, const int* in_sizes, int n_in,
                              void* d_out, int out_size) {
    const float* feat        = (const float*)d_in[0];
    const int*   indices     = (const int*)d_in[1];   // [2, E]
    const float* values      = (const float*)d_in[2]; // [E, 1]
    const float* temperature = (const float*)d_in[3];
    const float* w1          = (const float*)d_in[4]; // [257, 128]
    const float* b1          = (const float*)d_in[5];
    const float* w2          = (const float*)d_in[6]; // [128, 128]
    const float* b2          = (const float*)d_in[7];
    const float* w3          = (const float*)d_in[8]; // [128, 1]
    const float* b3          = (const float*)d_in[9];
    float* out = (float*)d_out;

    const int* colIdx = indices + EDGES;  // indices[1]

    const size_t smem1 = K1_SMEM_FLOATS * sizeof(float);
    const size_t smem2 = K2_SMEM_FLOATS * sizeof(float);
    cudaFuncSetAttribute(layer1_gemm_kernel,
                         cudaFuncAttributeMaxDynamicSharedMemorySize, (int)smem1);
    cudaFuncSetAttribute(edge_mlp_mask_kernel,
                         cudaFuncAttributeMaxDynamicSharedMemorySize, (int)smem2);

    dim3 g1((NN + 63) / 64, 2 * DIM / 64);  // 782 x 4
    layer1_gemm_kernel<<<g1, 256, smem1>>>(feat, w1);

    edge_mlp_mask_kernel<<<EDGES / EPB, K2T, smem2>>>(
        colIdx, values, temperature, w1, b1, w2, b2, w3, b3, out);
}

// round 4
// speedup vs baseline: 1.5188x; 1.5188x over previous
#include <cuda_runtime.h>
#include <cuda_bf16.h>
#include <math.h>

// Problem constants (fixed by the dataset)
#define NN    50000
#define DEG   16
#define EDGES (NN * DEG)      // 800000
#define DIM   128
#define HID   128

#define NPB   16              // nodes per block (kernel 2)
#define EPB   256             // edges per block
#define K2T   512             // threads (kernel 2)
#define H1SR  260             // h1T row stride (floats), multiple of 4

typedef unsigned long long ull;

#define FMA_F32X2(acc, a, b) \
    asm("fma.rn.f32x2 %0, %1, %2, %0;" : "+l"(acc) : "l"(a), "l"(b))
#define PACK_F32X2(out, lo, hi) \
    asm("mov.b64 %0, {%1, %2};" : "=l"(out) : "r"(lo), "r"(hi))
#define UNPACK_F32X2(lo, hi, in) \
    asm("mov.b64 {%0, %1}, %2;" : "=r"(lo), "=r"(hi) : "l"(in))

// Persistent scratch: layer-1 node projections A = F @ W1[0:128], B = F @ W1[128:256]
__device__ float g_A[NN * DIM];
__device__ float g_B[NN * DIM];

// ---------------------------------------------------------------------------
// Kernel 1: AB = features[N,128] @ Wcat[128,256]. Tiled fp32 GEMM.
// ---------------------------------------------------------------------------
#define K1_SMEM_FLOATS (64 * 132 + 128 * 68)

__global__ void layer1_gemm_kernel(const float* __restrict__ feat,
                                   const float* __restrict__ w1) {
    extern __shared__ float smem1[];
    float* featS = smem1;              // [64][132]
    float* wS    = smem1 + 64 * 132;   // [128][68]

    const int tid = threadIdx.x;
    const int m0 = blockIdx.x * 64;
    const int n0 = blockIdx.y * 64;

    for (int t = tid; t < 64 * 32; t += 256) {
        int r = t >> 5, c4 = (t & 31) << 2;
        int gr = m0 + r;
        float4 v = make_float4(0.f, 0.f, 0.f, 0.f);
        if (gr < NN) v = *(const float4*)&feat[gr * DIM + c4];
        *(float4*)&featS[r * 132 + c4] = v;
    }
    for (int t = tid; t < 128 * 16; t += 256) {
        int k = t >> 4, c4 = (t & 15) << 2;
        int n = n0 + c4;
        const float* src = (n < 128) ? &w1[k * 128 + n]
                                     : &w1[(128 + k) * 128 + (n - 128)];
        *(float4*)&wS[k * 68 + c4] = *(const float4*)src;
    }
    __syncthreads();

    const int ty = tid >> 4, tx = tid & 15;
    const int r0 = ty * 4, c0 = tx * 4;
    float acc[4][4];
#pragma unroll
    for (int i = 0; i < 4; ++i)
#pragma unroll
        for (int j = 0; j < 4; ++j) acc[i][j] = 0.f;

#pragma unroll 4
    for (int k = 0; k < 128; ++k) {
        float a[4];
#pragma unroll
        for (int i = 0; i < 4; ++i) a[i] = featS[(r0 + i) * 132 + k];
        float4 bq = *(const float4*)&wS[k * 68 + c0];
        float b[4] = {bq.x, bq.y, bq.z, bq.w};
#pragma unroll
        for (int i = 0; i < 4; ++i)
#pragma unroll
            for (int j = 0; j < 4; ++j) acc[i][j] = fmaf(a[i], b[j], acc[i][j]);
    }

#pragma unroll
    for (int i = 0; i < 4; ++i) {
        int node = m0 + r0 + i;
        if (node >= NN) continue;
        int n = n0 + c0;
        float4 o = make_float4(acc[i][0], acc[i][1], acc[i][2], acc[i][3]);
        if (n < 128) *(float4*)&g_A[node * DIM + n] = o;
        else         *(float4*)&g_B[node * DIM + (n - 128)] = o;
    }
}

// ---------------------------------------------------------------------------
// Kernel 2: per block = 16 nodes = 256 edges, 512 threads.
//  Phase 1: h1T[j][el] = relu(A[row]+B[col]+v*w1[256,j]+b1[j])
//           j across lanes -> g_B row reads COALESCED; float4 edge-quad stores.
//  Phase 2: warp tile = 128 edges x 16 cols; packed f32x2 FMAs (2 cols/op),
//           w2 read as 64-bit col-pairs (warp-uniform broadcast), h1 coalesced.
//  Phase 3: per-node softmax -> hard-concrete -> softmax -> top-8 mask.
// ---------------------------------------------------------------------------
#define K2_SMEM_FLOATS (128 * H1SR + 128 * 128 + EPB * 9 + 4 * 128 + 3 * EPB)

__global__ void __launch_bounds__(K2T, 1)
edge_mlp_mask_kernel(const int* __restrict__ colIdx,
                     const float* __restrict__ values,
                     const float* __restrict__ temperature,
                     const float* __restrict__ w1,
                     const float* __restrict__ b1,
                     const float* __restrict__ w2,
                     const float* __restrict__ b2,
                     const float* __restrict__ w3,
                     const float* __restrict__ b3,
                     float* __restrict__ out) {
    extern __shared__ float smem[];
    float* h1T   = smem;                      // [128(j)][260]
    float* w2s   = h1T + 128 * H1SR;          // [128(k)][128(j)]
    float* zred  = w2s + 128 * 128;           // [256(el)][9]
    float* b2s   = zred + EPB * 9;            // [128]
    float* w3s   = b2s + 128;                 // [128]
    float* b1s   = w3s + 128;                 // [128]
    float* w1rs  = b1s + 128;                 // [128]
    float* vals  = w1rs + 128;                // [256]
    float* zz    = vals + EPB;                // [256]
    int*   cols  = (int*)(zz + EPB);          // [256]

    const int tid = threadIdx.x;
    const int base_node = blockIdx.x * NPB;
    const int e0 = blockIdx.x * EPB;

    // ---- stage w2, b1/b2/w3, w1 value-row, colIdx, values ----
    for (int t = tid; t < 128 * 32; t += K2T) {
        int k = t >> 5, c4 = (t & 31) << 2;
        *(float4*)&w2s[k * 128 + c4] = *(const float4*)&w2[k * 128 + c4];
    }
    if (tid < 128) {
        b2s[tid]  = b2[tid];
        w3s[tid]  = w3[tid];
        b1s[tid]  = b1[tid];
        w1rs[tid] = w1[256 * 128 + tid];
    }
    {
        int t2 = tid - 128;
        if (t2 >= 0 && t2 < EPB) {
            cols[t2] = colIdx[e0 + t2];
            vals[t2] = values[e0 + t2];
        }
    }
    __syncthreads();

    // ---- Phase 1: j across lanes (coalesced g_B rows), 4-edge quads ----
    {
        const int j = tid & 127;                 // feature, consecutive in warp
        const int g = tid >> 7;                  // 0..3 -> 64-edge group
        const float b1j = b1s[j];
        const float wrj = w1rs[j];
#pragma unroll
        for (int nn = 0; nn < 4; ++nn) {         // node within group
            const int node = g * 4 + nn;
            const float a = g_A[(base_node + node) * DIM + j] + b1j;
#pragma unroll
            for (int q = 0; q < 4; ++q) {        // edge quad within node
                const int el = node * 16 + q * 4;
                int4   c4 = *(const int4*)&cols[el];
                float4 v4 = *(const float4*)&vals[el];
                float4 h;
                h.x = fmaf(v4.x, wrj, a + g_B[c4.x * DIM + j]);
                h.y = fmaf(v4.y, wrj, a + g_B[c4.y * DIM + j]);
                h.z = fmaf(v4.z, wrj, a + g_B[c4.z * DIM + j]);
                h.w = fmaf(v4.w, wrj, a + g_B[c4.w * DIM + j]);
                h.x = fmaxf(h.x, 0.f); h.y = fmaxf(h.y, 0.f);
                h.z = fmaxf(h.z, 0.f); h.w = fmaxf(h.w, 0.f);
                h1T[j * H1SR + el + 0] = h.x;
                h1T[j * H1SR + el + 1] = h.y;
                h1T[j * H1SR + el + 2] = h.z;
                h1T[j * H1SR + el + 3] = h.w;
            }
        }
    }
    __syncthreads();

    // ---- Phase 2: packed f32x2 GEMM + fused relu + w3 partial dot ----
    {
        const int w    = tid >> 5;        // warp 0..15
        const int lane = tid & 31;
        const int eh   = w >> 3;          // edge half (0/1)
        const int grp  = w & 7;           // col group (0..7)
        const int er0  = eh * 128 + lane * 4;   // 4 consecutive edges
        const int jc0  = grp * 16;              // 16 cols = 8 col-pairs

        ull acc[4][8];
#pragma unroll
        for (int i = 0; i < 4; ++i)
#pragma unroll
            for (int p = 0; p < 8; ++p) acc[i][p] = 0ull;

#pragma unroll 2
        for (int k = 0; k < 128; ++k) {
            // a: 4 edges, coalesced LDS.128
            float4 a4 = *(const float4*)&h1T[k * H1SR + er0];
            ull pa[4];
            PACK_F32X2(pa[0], __float_as_uint(a4.x), __float_as_uint(a4.x));
            PACK_F32X2(pa[1], __float_as_uint(a4.y), __float_as_uint(a4.y));
            PACK_F32X2(pa[2], __float_as_uint(a4.z), __float_as_uint(a4.z));
            PACK_F32X2(pa[3], __float_as_uint(a4.w), __float_as_uint(a4.w));
            // b: 8 col-pairs, warp-uniform broadcast (read as 64-bit pairs)
            const ulonglong2* wp = (const ulonglong2*)&w2s[k * 128 + jc0];
            ull pb[8];
            ulonglong2 b01 = wp[0]; pb[0] = b01.x; pb[1] = b01.y;
            ulonglong2 b23 = wp[1]; pb[2] = b23.x; pb[3] = b23.y;
            ulonglong2 b45 = wp[2]; pb[4] = b45.x; pb[5] = b45.y;
            ulonglong2 b67 = wp[3]; pb[6] = b67.x; pb[7] = b67.y;
#pragma unroll
            for (int i = 0; i < 4; ++i)
#pragma unroll
                for (int p = 0; p < 8; ++p)
                    FMA_F32X2(acc[i][p], pa[i], pb[p]);
        }
        // epilogue: unpack, +b2, relu, w3 partial dot (col-ascending order)
#pragma unroll
        for (int i = 0; i < 4; ++i) {
            float s = 0.f;
#pragma unroll
            for (int p = 0; p < 8; ++p) {
                unsigned lo, hi;
                UNPACK_F32X2(lo, hi, acc[i][p]);
                float h2a = fmaxf(__uint_as_float(lo) + b2s[jc0 + 2 * p], 0.f);
                s = fmaf(h2a, w3s[jc0 + 2 * p], s);
                float h2b = fmaxf(__uint_as_float(hi) + b2s[jc0 + 2 * p + 1], 0.f);
                s = fmaf(h2b, w3s[jc0 + 2 * p + 1], s);
            }
            zred[(er0 + i) * 9 + grp] = s;
        }
    }
    __syncthreads();

    if (tid < EPB) {
        float s = b3[0];
#pragma unroll
        for (int g = 0; g < 8; ++g) s += zred[tid * 9 + g];
        zz[tid] = s;
    }
    __syncthreads();

    // ---- Phase 3: per-node (warp -> node) softmax chain + top-8 mask ----
    {
        const unsigned FULL = 0xffffffffu;
        const int lane = tid & 31;
        const int l = lane & 15;
        const int wnode = tid >> 5;          // 0..15
        const int el = wnode * 16 + l;
        const float zv = zz[el];

        float m = zv;
#pragma unroll
        for (int o = 8; o >= 1; o >>= 1) m = fmaxf(m, __shfl_xor_sync(FULL, m, o, 16));
        float x1 = __fsub_rn(zv, m);
        float ev = (float)exp((double)x1);
        float s = 0.f;
#pragma unroll
        for (int o = 0; o < 16; ++o) s = __fadd_rn(s, __shfl_sync(FULL, ev, o, 16));
        float pi = __fdiv_rn(ev, s);

        float larg = __fadd_rn(pi, 1e-8f);
        float lg = (float)log((double)larg);
        float sx = __fdiv_rn(lg, temperature[0]);
        float hard = (float)(1.0 / (1.0 + exp(-(double)sx)));
        hard = fminf(fmaxf(hard, 0.f), 1.f);

        float m2 = hard;
#pragma unroll
        for (int o = 8; o >= 1; o >>= 1) m2 = fmaxf(m2, __shfl_xor_sync(FULL, m2, o, 16));
        float x2 = __fsub_rn(hard, m2);
        float e2 = (float)exp((double)x2);
        float s2 = 0.f;
#pragma unroll
        for (int o = 0; o < 16; ++o) s2 = __fadd_rn(s2, __shfl_sync(FULL, e2, o, 16));
        float y = __fdiv_rn(e2, s2);

        int r = 0;
#pragma unroll
        for (int o = 0; o < 16; ++o) {
            float yo = __shfl_sync(FULL, y, o, 16);
            r += (yo > y) || (yo == y && o < l);
        }
        unsigned bal = __ballot_sync(FULL, (r == 7) && (lane < 16));
        int src = __ffs(bal) - 1;
        float thre = __shfl_sync(FULL, y, src);

        float t = __fadd_rn(__fsub_rn(y, thre), 1e-7f);
        float outv = (t > 0.f) ? y : 0.f;
        if (lane < 16) out[e0 + el] = outv;
    }
}

// ---------------------------------------------------------------------------
extern "C" void kernel_launch(void* const* d_in, const int* in_sizes, int n_in,
                              void* d_out, int out_size) {
    const float* feat        = (const float*)d_in[0];
    const int*   indices     = (const int*)d_in[1];   // [2, E]
    const float* values      = (const float*)d_in[2]; // [E, 1]
    const float* temperature = (const float*)d_in[3];
    const float* w1          = (const float*)d_in[4]; // [257, 128]
    const float* b1          = (const float*)d_in[5];
    const float* w2          = (const float*)d_in[6]; // [128, 128]
    const float* b2          = (const float*)d_in[7];
    const float* w3          = (const float*)d_in[8]; // [128, 1]
    const float* b3          = (const float*)d_in[9];
    float* out = (float*)d_out;

    const int* colIdx = indices + EDGES;  // indices[1]

    const size_t smem1 = K1_SMEM_FLOATS * sizeof(float);
    const size_t smem2 = K2_SMEM_FLOATS * sizeof(float);
    cudaFuncSetAttribute(layer1_gemm_kernel,
                         cudaFuncAttributeMaxDynamicSharedMemorySize, (int)smem1);
    cudaFuncSetAttribute(edge_mlp_mask_kernel,
                         cudaFuncAttributeMaxDynamicSharedMemorySize, (int)smem2);

    dim3 g1((NN + 63) / 64, 2 * DIM / 64);  // 782 x 4
    layer1_gemm_kernel<<<g1, 256, smem1>>>(feat, w1);

    edge_mlp_mask_kernel<<<EDGES / EPB, K2T, smem2>>>(
        colIdx, values, temperature, w1, b1, w2, b2, w3, b3, out);
}